// round 11
// baseline (speedup 1.0000x reference)
#include <cuda_runtime.h>
#include <math.h>

#define BATCH 64
#define TT 512
#define II 512
#define HH 512

typedef unsigned long long ull;

__device__ __forceinline__ ull pack2(float x, float y) {
    ull r; asm("mov.b64 %0, {%1, %2};" : "=l"(r) : "f"(x), "f"(y)); return r;
}
__device__ __forceinline__ void unpack2(ull v, float& x, float& y) {
    asm("mov.b64 {%0, %1}, %2;" : "=f"(x), "=f"(y) : "l"(v));
}
__device__ __forceinline__ ull ffma2(ull a, ull b, ull c) {
    ull d; asm("fma.rn.f32x2 %0, %1, %2, %3;" : "=l"(d) : "l"(a), "l"(b), "l"(c)); return d;
}
__device__ __forceinline__ ull fadd2(ull a, ull b) {
    ull d; asm("add.rn.f32x2 %0, %1, %2;" : "=l"(d) : "l"(a), "l"(b)); return d;
}
__device__ __forceinline__ unsigned ld_acq(const unsigned* p) {
    unsigned v; asm volatile("ld.acquire.gpu.global.u32 %0, [%1];" : "=r"(v) : "l"(p) : "memory");
    return v;
}
__device__ __forceinline__ void red_rel_add1(unsigned* p) {
    asm volatile("red.release.gpu.global.add.u32 [%0], 1;" :: "l"(p) : "memory");
}
__device__ __forceinline__ float tanh_fast(float x) {
    float ax = fabsf(x);
    if (ax < 0.04f) return x * (1.0f - 0.3333333f * x * x);
    float e = __expf(2.0f * x);
    return 1.0f - __fdividef(2.0f, e + 1.0f);
}

// persistent state: h transposed [j][b] ping-pong; 16 group counters (4 batches each)
__device__ float    g_hT[2][HH][BATCH];
__device__ unsigned g_bar[16 * 32];     // 128B apart

// ---------------------------------------------------------------------------
// Phase 1: xw = X @ Wx + bx + bh  (R2 fp32 version — fastest measured)
// ---------------------------------------------------------------------------
__global__ __launch_bounds__(256, 2) void gemm_xw_kernel(
    const float* __restrict__ X, const float* __restrict__ Wx,
    const float* __restrict__ bx, const float* __restrict__ bh,
    float* __restrict__ out)
{
    __shared__ float As[2][8][128];
    __shared__ float Bs[2][8][128];

    const int tid = threadIdx.x;
    const int bm = blockIdx.y * 128, bn = blockIdx.x * 128;
    const int ty = tid >> 4, tx = tid & 15;
    const int arow = tid >> 1, akc = (tid & 1) * 4;
    const int brow = tid >> 5, bcc = (tid & 31) * 4;

    const float* Ag = X + (size_t)(bm + arow) * II + akc;
    const float* Bg = Wx + (size_t)brow * HH + bn + bcc;

    {
        float4 av = *(const float4*)Ag;
        float4 bv = *(const float4*)Bg;
        As[0][akc+0][arow] = av.x; As[0][akc+1][arow] = av.y;
        As[0][akc+2][arow] = av.z; As[0][akc+3][arow] = av.w;
        *(float4*)&Bs[0][brow][bcc] = bv;
    }
    __syncthreads();

    ull acc[8][4];
#pragma unroll
    for (int i = 0; i < 8; i++)
#pragma unroll
        for (int j = 0; j < 4; j++) acc[i][j] = 0ull;

    const int NT = II / 8;
    for (int kt = 0; kt < NT; kt++) {
        const int cur = kt & 1;
        float4 av, bv;
        if (kt + 1 < NT) {
            av = *(const float4*)(Ag + (kt + 1) * 8);
            bv = *(const float4*)(Bg + (size_t)(kt + 1) * 8 * HH);
        }
#pragma unroll
        for (int kk = 0; kk < 8; kk++) {
            float4 a0 = *(const float4*)&As[cur][kk][ty * 8];
            float4 a1 = *(const float4*)&As[cur][kk][ty * 8 + 4];
            float4 b0 = *(const float4*)&Bs[cur][kk][tx * 8];
            float4 b1 = *(const float4*)&Bs[cur][kk][tx * 8 + 4];
            ull bp[4] = { pack2(b0.x,b0.y), pack2(b0.z,b0.w),
                          pack2(b1.x,b1.y), pack2(b1.z,b1.w) };
            float aa[8] = { a0.x,a0.y,a0.z,a0.w, a1.x,a1.y,a1.z,a1.w };
#pragma unroll
            for (int i = 0; i < 8; i++) {
                ull ap = pack2(aa[i], aa[i]);
#pragma unroll
                for (int j = 0; j < 4; j++) acc[i][j] = ffma2(ap, bp[j], acc[i][j]);
            }
        }
        if (kt + 1 < NT) {
            const int nxt = cur ^ 1;
            __syncthreads();
            As[nxt][akc+0][arow] = av.x; As[nxt][akc+1][arow] = av.y;
            As[nxt][akc+2][arow] = av.z; As[nxt][akc+3][arow] = av.w;
            *(float4*)&Bs[nxt][brow][bcc] = bv;
            __syncthreads();
        }
    }

    const int n0 = bn + tx * 8;
    float bias[8];
#pragma unroll
    for (int j = 0; j < 8; j++) bias[j] = bx[n0 + j] + bh[n0 + j];
#pragma unroll
    for (int i = 0; i < 8; i++) {
        const int m = bm + ty * 8 + i;
        float o[8];
#pragma unroll
        for (int j = 0; j < 4; j++) unpack2(acc[i][j], o[j*2], o[j*2+1]);
        float4 v0 = make_float4(o[0]+bias[0], o[1]+bias[1], o[2]+bias[2], o[3]+bias[3]);
        float4 v1 = make_float4(o[4]+bias[4], o[5]+bias[5], o[6]+bias[6], o[7]+bias[7]);
        *(float4*)&out[(size_t)m * HH + n0]     = v0;
        *(float4*)&out[(size_t)m * HH + n0 + 4] = v1;
    }
}

// ---------------------------------------------------------------------------
// Phase 2: DUAL-CHAIN recurrence. 128 CTAs x 256 thr.
// 16 groups of 4 batches. CTA (gp 0..7, cg 0..15) runs chain A (group gp)
// and chain B (group gp+8), both on cols [32cg, 32cg+32). Chains alternate
// each iteration so each chain's flag/store latency hides under the other's
// compute. Weights shared between chains (same col slice).
// ---------------------------------------------------------------------------
#define CHAIN_STEP(hS, pS, barS, b0, redc, xv0, xv1, rb0)                     \
    {                                                                          \
        ull acc00 = 0ull, acc01 = 0ull, acc10 = 0ull, acc11 = 0ull;            \
        if (t > 0) {                                                           \
            if (lane == 0) {                                                   \
                const unsigned tgt = (unsigned)t * 32u;                        \
                while (ld_acq(barS) < tgt) { }                                 \
            }                                                                  \
            __syncwarp();                                                      \
            {                                                                  \
                const float* gsrc = &g_hT[t & 1][0][b0];                       \
                float4 va = __ldcg((const float4*)(gsrc + (size_t)tid * BATCH));          \
                float4 vb = __ldcg((const float4*)(gsrc + (size_t)(tid + 256) * BATCH));  \
                *(float4*)&hS[tid * 4] = va;                                   \
                *(float4*)&hS[(tid + 256) * 4] = vb;                           \
            }                                                                  \
            __syncthreads();                                                   \
            const ulonglong2* hb = (const ulonglong2*)&hS[kt * 32 * 4];        \
            _Pragma("unroll")                                                  \
            for (int i = 0; i < 32; i++) {                                     \
                ulonglong2 u = hb[i];                                          \
                ull w0 = w2[i][0], w1 = w2[i][1];                              \
                acc00 = ffma2(u.x, w0, acc00);                                 \
                acc01 = ffma2(u.y, w0, acc01);                                 \
                acc10 = ffma2(u.x, w1, acc10);                                 \
                acc11 = ffma2(u.y, w1, acc11);                                 \
            }                                                                  \
        }                                                                      \
        ull v0, v1;                                                            \
        {                                                                      \
            ull give = hl ? acc00 : acc10;                                     \
            ull got  = __shfl_xor_sync(0xFFFFFFFFu, give, 16);                 \
            v0 = fadd2(hl ? acc10 : acc00, got);                               \
            give = hl ? acc01 : acc11;                                         \
            got  = __shfl_xor_sync(0xFFFFFFFFu, give, 16);                     \
            v1 = fadd2(hl ? acc11 : acc01, got);                               \
        }                                                                      \
        pS[lane * 17 + w * 2 + 0] = v0;                                        \
        pS[lane * 17 + w * 2 + 1] = v1;                                        \
        __syncthreads();                                                       \
        if (redc) {                                                            \
            ull ssum = pS[rlane * 17 + rp];                                    \
            _Pragma("unroll")                                                  \
            for (int ww = 1; ww < 8; ww++)                                     \
                ssum = fadd2(ssum, pS[rlane * 17 + ww * 2 + rp]);              \
            float a0, a1; unpack2(ssum, a0, a1);                               \
            float r0 = tanh_fast(xv0 + a0);                                    \
            float r1 = tanh_fast(xv1 + a1);                                    \
            mem[((size_t)(rb0) * TT + t) * HH + rj] = r0;                      \
            mem[((size_t)((rb0) + 1) * TT + t) * HH + rj] = r1;                \
            *(float2*)&g_hT[(t + 1) & 1][rj][rb0] = make_float2(r0, r1);       \
            if (t == TT - 1) {                                                 \
                hid[(size_t)(rb0) * HH + rj] = r0;                             \
                hid[(size_t)((rb0) + 1) * HH + rj] = r1;                       \
            } else {                                                           \
                __syncwarp();                                                  \
                if (lane == 0) red_rel_add1(barS);                             \
            }                                                                  \
        }                                                                      \
    }

__global__ __launch_bounds__(256, 1) void rnn_kernel(
    const float* __restrict__ Wh, float* __restrict__ out)
{
    __shared__ float hA[HH * 4];       // 8KB
    __shared__ float hB[HH * 4];       // 8KB
    __shared__ ull   pA[32 * 17];      // ~4.3KB
    __shared__ ull   pB[32 * 17];

    const int tid  = threadIdx.x;
    const int lane = tid & 31;
    const int w    = tid >> 5;
    const int jq   = lane & 15;
    const int hl   = lane >> 4;
    const int kt   = (w << 1) | hl;       // 0..15, k-chunk of 32
    const int cg   = blockIdx.x & 15;
    const int gp   = blockIdx.x >> 4;     // 0..7
    const int jbase = cg * 32;
    const int bA = gp * 4;
    const int bB = (gp + 8) * 4;

    // weights: w2[i][c] = dup(Wh[kt*32+i][jbase + jq*2 + c]) — shared by chains
    ull w2[32][2];
#pragma unroll
    for (int i = 0; i < 32; i++) {
        float2 wv = *(const float2*)&Wh[(size_t)(kt * 32 + i) * HH + jbase + jq * 2];
        w2[i][0] = pack2(wv.x, wv.x);
        w2[i][1] = pack2(wv.y, wv.y);
    }

    // reducer mapping: tid<64 -> chain A, 64..127 -> chain B
    const int s   = tid & 63;
    const int rjc = s & 31;
    const int rp  = (s >> 5) & 1;               // batch pair
    const int rj  = jbase + rjc;
    const int rlane = ((rjc & 1) << 4) | (rjc >> 1);
    const bool redA = (tid < 64);
    const bool redB = (tid >= 64) && (tid < 128);
    const int rb0A = bA + rp * 2;
    const int rb0B = bB + rp * 2;

    float* mem = out;
    float* hid = out + (size_t)BATCH * TT * HH;
    unsigned* barA = &g_bar[gp * 32];
    unsigned* barB = &g_bar[(gp + 8) * 32];

    for (int t = 0; t < TT; t++) {
        float xa0 = 0.f, xa1 = 0.f, xb0 = 0.f, xb1 = 0.f;
        if (redA) {
            xa0 = __ldg(&mem[((size_t)rb0A * TT + t) * HH + rj]);
            xa1 = __ldg(&mem[((size_t)(rb0A + 1) * TT + t) * HH + rj]);
        }
        if (redB) {
            xb0 = __ldg(&mem[((size_t)rb0B * TT + t) * HH + rj]);
            xb1 = __ldg(&mem[((size_t)(rb0B + 1) * TT + t) * HH + rj]);
        }

        CHAIN_STEP(hA, pA, barA, bA, redA, xa0, xa1, rb0A)
        CHAIN_STEP(hB, pB, barB, bB, redB, xb0, xb1, rb0B)
    }

    // replay reset: every CTA arrives once on both bars; cg0 waits + zeroes
    __syncthreads();
    if (tid == 0) {
        red_rel_add1(barA);
        red_rel_add1(barB);
        if (cg == 0) {
            const unsigned full = 511u * 32u + 16u;
            while (ld_acq(barA) < full) { }
            while (ld_acq(barB) < full) { }
            atomicExch(barA, 0u);
            atomicExch(barB, 0u);
        }
    }
}

// ---------------------------------------------------------------------------
extern "C" void kernel_launch(void* const* d_in, const int* in_sizes, int n_in,
                              void* d_out, int out_size) {
    const float* x  = (const float*)d_in[0];
    const float* Wx = (const float*)d_in[1];
    const float* Wh = (const float*)d_in[2];
    const float* bx = (const float*)d_in[3];
    const float* bh = (const float*)d_in[4];
    float* out = (float*)d_out;

    dim3 ggrid(HH / 128, (BATCH * TT) / 128);   // (4, 256)
    gemm_xw_kernel<<<ggrid, 256>>>(x, Wx, bx, bh, out);
    rnn_kernel<<<128, 256>>>(Wh, out);
}

// round 12
// speedup vs baseline: 1.0735x; 1.0735x over previous
#include <cuda_runtime.h>
#include <math.h>

#define BATCH 64
#define TT 512
#define II 512
#define HH 512
#define NG 8      // batch groups (8 batches each)
#define CPG 16    // CTAs per group (32 cols each)

typedef unsigned long long ull;

__device__ __forceinline__ ull pack2(float x, float y) {
    ull r; asm("mov.b64 %0, {%1, %2};" : "=l"(r) : "f"(x), "f"(y)); return r;
}
__device__ __forceinline__ void unpack2(ull v, float& x, float& y) {
    asm("mov.b64 {%0, %1}, %2;" : "=f"(x), "=f"(y) : "l"(v));
}
__device__ __forceinline__ ull ffma2(ull a, ull b, ull c) {
    ull d; asm("fma.rn.f32x2 %0, %1, %2, %3;" : "=l"(d) : "l"(a), "l"(b), "l"(c)); return d;
}
__device__ __forceinline__ ull fadd2(ull a, ull b) {
    ull d; asm("add.rn.f32x2 %0, %1, %2;" : "=l"(d) : "l"(a), "l"(b)); return d;
}
__device__ __forceinline__ unsigned ld_acq(const unsigned* p) {
    unsigned v; asm volatile("ld.acquire.gpu.global.u32 %0, [%1];" : "=r"(v) : "l"(p) : "memory");
    return v;
}
__device__ __forceinline__ void red_rel_add1(unsigned* p) {
    asm volatile("red.release.gpu.global.add.u32 [%0], 1;" :: "l"(p) : "memory");
}
__device__ __forceinline__ float tanh_fast(float x) {
    float ax = fabsf(x);
    if (ax < 0.04f) return x * (1.0f - 0.3333333f * x * x);
    float e = __expf(2.0f * x);
    return 1.0f - __fdividef(2.0f, e + 1.0f);
}

// persistent state: h transposed [j][b] ping-pong; per-CTA step counters
__device__ float    g_hT[2][HH][BATCH];
__device__ unsigned g_cnt[NG * 32];     // 16 counters per group (one line)
__device__ unsigned g_done[NG * 32];

// ---------------------------------------------------------------------------
// Phase 1: xw = X @ Wx + bx + bh  (R2 fp32 version — fastest measured)
// ---------------------------------------------------------------------------
__global__ __launch_bounds__(256, 2) void gemm_xw_kernel(
    const float* __restrict__ X, const float* __restrict__ Wx,
    const float* __restrict__ bx, const float* __restrict__ bh,
    float* __restrict__ out)
{
    __shared__ float As[2][8][128];
    __shared__ float Bs[2][8][128];

    const int tid = threadIdx.x;
    const int bm = blockIdx.y * 128, bn = blockIdx.x * 128;
    const int ty = tid >> 4, tx = tid & 15;
    const int arow = tid >> 1, akc = (tid & 1) * 4;
    const int brow = tid >> 5, bcc = (tid & 31) * 4;

    const float* Ag = X + (size_t)(bm + arow) * II + akc;
    const float* Bg = Wx + (size_t)brow * HH + bn + bcc;

    {
        float4 av = *(const float4*)Ag;
        float4 bv = *(const float4*)Bg;
        As[0][akc+0][arow] = av.x; As[0][akc+1][arow] = av.y;
        As[0][akc+2][arow] = av.z; As[0][akc+3][arow] = av.w;
        *(float4*)&Bs[0][brow][bcc] = bv;
    }
    __syncthreads();

    ull acc[8][4];
#pragma unroll
    for (int i = 0; i < 8; i++)
#pragma unroll
        for (int j = 0; j < 4; j++) acc[i][j] = 0ull;

    const int NT = II / 8;
    for (int kt = 0; kt < NT; kt++) {
        const int cur = kt & 1;
        float4 av, bv;
        if (kt + 1 < NT) {
            av = *(const float4*)(Ag + (kt + 1) * 8);
            bv = *(const float4*)(Bg + (size_t)(kt + 1) * 8 * HH);
        }
#pragma unroll
        for (int kk = 0; kk < 8; kk++) {
            float4 a0 = *(const float4*)&As[cur][kk][ty * 8];
            float4 a1 = *(const float4*)&As[cur][kk][ty * 8 + 4];
            float4 b0 = *(const float4*)&Bs[cur][kk][tx * 8];
            float4 b1 = *(const float4*)&Bs[cur][kk][tx * 8 + 4];
            ull bp[4] = { pack2(b0.x,b0.y), pack2(b0.z,b0.w),
                          pack2(b1.x,b1.y), pack2(b1.z,b1.w) };
            float aa[8] = { a0.x,a0.y,a0.z,a0.w, a1.x,a1.y,a1.z,a1.w };
#pragma unroll
            for (int i = 0; i < 8; i++) {
                ull ap = pack2(aa[i], aa[i]);
#pragma unroll
                for (int j = 0; j < 4; j++) acc[i][j] = ffma2(ap, bp[j], acc[i][j]);
            }
        }
        if (kt + 1 < NT) {
            const int nxt = cur ^ 1;
            __syncthreads();
            As[nxt][akc+0][arow] = av.x; As[nxt][akc+1][arow] = av.y;
            As[nxt][akc+2][arow] = av.z; As[nxt][akc+3][arow] = av.w;
            *(float4*)&Bs[nxt][brow][bcc] = bv;
            __syncthreads();
        }
    }

    const int n0 = bn + tx * 8;
    float bias[8];
#pragma unroll
    for (int j = 0; j < 8; j++) bias[j] = bx[n0 + j] + bh[n0 + j];
#pragma unroll
    for (int i = 0; i < 8; i++) {
        const int m = bm + ty * 8 + i;
        float o[8];
#pragma unroll
        for (int j = 0; j < 4; j++) unpack2(acc[i][j], o[j*2], o[j*2+1]);
        float4 v0 = make_float4(o[0]+bias[0], o[1]+bias[1], o[2]+bias[2], o[3]+bias[3]);
        float4 v1 = make_float4(o[4]+bias[4], o[5]+bias[5], o[6]+bias[6], o[7]+bias[7]);
        *(float4*)&out[(size_t)m * HH + n0]     = v0;
        *(float4*)&out[(size_t)m * HH + n0 + 4] = v1;
    }
}

// ---------------------------------------------------------------------------
// Phase 2: recurrence with WARP-AUTONOMOUS band consumption.
// 128 CTAs x 256 thr; CTA (g 0..7, cg 0..15): 8 batches x 32 cols.
// Counters: g_cnt[g*32+cg] += 1 per reducer warp per step (value 4(t+1)).
// Warp w depends only on producers cg=2w, 2w+1: polls their counters, stages
// its own k-band [64w,64w+64) (warp-local smem slice), computes immediately.
// One __syncthreads before the cross-warp reduce. Core math = R7 verbatim.
// ---------------------------------------------------------------------------
#define PIDX(l, w_, p_) ((l) * 33 + (w_) * 4 + (p_))

__global__ __launch_bounds__(256, 1) void rnn_kernel(
    const float* __restrict__ Wh, float* __restrict__ out)
{
    __shared__ float h_Ts[HH * 8];        // [k][8 batches], 16KB
    __shared__ ull   part[32 * 33];       // padded, ~8.4KB

    const int tid  = threadIdx.x;
    const int lane = tid & 31;
    const int w    = tid >> 5;
    const int jq   = lane & 15;
    const int hl   = lane >> 4;
    const int kt   = (w << 1) | hl;       // 0..15, k-chunk of 32
    const int cg   = blockIdx.x & 15;
    const int g    = blockIdx.x >> 4;
    const int jbase = cg * 32;
    const int bbase = g * 8;

    // weights: w2[i][c] = dup(Wh[kt*32+i][jbase + jq*2 + c])
    ull w2[32][2];
#pragma unroll
    for (int i = 0; i < 32; i++) {
        float2 wv = *(const float2*)&Wh[(size_t)(kt * 32 + i) * HH + jbase + jq * 2];
        w2[i][0] = pack2(wv.x, wv.x);
        w2[i][1] = pack2(wv.y, wv.y);
    }

    // reducer mapping (tid < 128)
    const int rjc = tid & 31;
    const int rp  = (tid >> 5) & 3;
    const int rb0 = bbase + rp * 2;
    const int rj  = jbase + rjc;
    const int rlane = ((rjc & 1) << 4) | (rjc >> 1);
    const bool is_red = (tid < 128);

    float* mem = out;
    float* hid = out + (size_t)BATCH * TT * HH;
    unsigned* cnt = &g_cnt[g * 32];
    unsigned* src0 = &cnt[2 * w];
    unsigned* src1 = &cnt[2 * w + 1];

    for (int t = 0; t < TT; t++) {
        float xw0 = 0.f, xw1 = 0.f;
        if (is_red) {
            xw0 = __ldg(&mem[((size_t)rb0 * TT + t) * HH + rj]);
            xw1 = __ldg(&mem[((size_t)(rb0 + 1) * TT + t) * HH + rj]);
        }

        ull acc[2][4];
#pragma unroll
        for (int p = 0; p < 4; p++) { acc[0][p] = 0ull; acc[1][p] = 0ull; }

        if (t > 0) {
            // warp-local wait on this band's two producer CTAs
            if (lane == 0) {
                const unsigned tgt = (unsigned)t * 4u;
                while (ld_acq(src0) < tgt) { }
                while (ld_acq(src1) < tgt) { }
            }
            __syncwarp();

            // warp-local staging of its own band: rows [64w, 64w+64)
            const float* gsrc = &g_hT[t & 1][0][0];
#pragma unroll
            for (int i = 0; i < 4; i++) {
                int e = lane + i * 32;            // 0..127
                int row = w * 64 + (e >> 1), q = e & 1;
                float4 v = __ldcg((const float4*)&gsrc[row * BATCH + bbase + q * 4]);
                *(float4*)&h_Ts[row * 8 + q * 4] = v;
            }
            __syncwarp();

            const ulonglong2* hb = (const ulonglong2*)&h_Ts[kt * 32 * 8];
#pragma unroll
            for (int i = 0; i < 32; i++) {
                ulonglong2 u0 = hb[2 * i], u1 = hb[2 * i + 1];
                ull w0 = w2[i][0], w1 = w2[i][1];
                acc[0][0] = ffma2(u0.x, w0, acc[0][0]);
                acc[0][1] = ffma2(u0.y, w0, acc[0][1]);
                acc[0][2] = ffma2(u1.x, w0, acc[0][2]);
                acc[0][3] = ffma2(u1.y, w0, acc[0][3]);
                acc[1][0] = ffma2(u0.x, w1, acc[1][0]);
                acc[1][1] = ffma2(u0.y, w1, acc[1][1]);
                acc[1][2] = ffma2(u1.x, w1, acc[1][2]);
                acc[1][3] = ffma2(u1.y, w1, acc[1][3]);
            }
        }

        // fold across lane bit 4
        ull v[4];
#pragma unroll
        for (int p = 0; p < 4; p++) {
            ull give = hl ? acc[0][p] : acc[1][p];
            ull got  = __shfl_xor_sync(0xFFFFFFFFu, give, 16);
            ull keep = hl ? acc[1][p] : acc[0][p];
            v[p] = fadd2(keep, got);
        }
#pragma unroll
        for (int p = 0; p < 4; p++) part[PIDX(lane, w, p)] = v[p];
        __syncthreads();

        if (is_red) {
            ull s = part[PIDX(rlane, 0, rp)];
#pragma unroll
            for (int ww = 1; ww < 8; ww++) s = fadd2(s, part[PIDX(rlane, ww, rp)]);
            float a0, a1; unpack2(s, a0, a1);
            float r0 = tanh_fast(xw0 + a0);
            float r1 = tanh_fast(xw1 + a1);
            mem[((size_t)rb0 * TT + t) * HH + rj] = r0;
            mem[((size_t)(rb0 + 1) * TT + t) * HH + rj] = r1;
            *(float2*)&g_hT[(t + 1) & 1][rj][rb0] = make_float2(r0, r1);
            if (t == TT - 1) {
                hid[(size_t)rb0 * HH + rj] = r0;
                hid[(size_t)(rb0 + 1) * HH + rj] = r1;
            }
            if (t < TT - 1) {
                // each reducer warp releases once its own h stores are issued
                __syncwarp();
                if (lane == 0) red_rel_add1(&cnt[cg]);
            }
        }
    }

    // replay reset: group handshake, then cg0 zeroes the 16 counters
    __syncthreads();
    if (tid == 0) {
        red_rel_add1(&g_done[g * 32]);
        if (cg == 0) {
            while (ld_acq(&g_done[g * 32]) < (unsigned)CPG) { }
#pragma unroll
            for (int i = 0; i < CPG; i++) atomicExch(&cnt[i], 0u);
            atomicExch(&g_done[g * 32], 0u);
        }
    }
}

// ---------------------------------------------------------------------------
extern "C" void kernel_launch(void* const* d_in, const int* in_sizes, int n_in,
                              void* d_out, int out_size) {
    const float* x  = (const float*)d_in[0];
    const float* Wx = (const float*)d_in[1];
    const float* Wh = (const float*)d_in[2];
    const float* bx = (const float*)d_in[3];
    const float* bh = (const float*)d_in[4];
    float* out = (float*)d_out;

    dim3 ggrid(HH / 128, (BATCH * TT) / 128);   // (4, 256)
    gemm_xw_kernel<<<ggrid, 256>>>(x, Wx, bx, bh, out);
    rnn_kernel<<<128, 256>>>(Wh, out);
}